// round 17
// baseline (speedup 1.0000x reference)
#include <cuda_runtime.h>
#include <math.h>
#include <cstdint>

#define BSZ  16
#define NCAP 1152
#define DP   8
#define DDIG 10
#define DD   16

#define TILE_N 32
#define NT   (NCAP / TILE_N)    // 36
#define NUA  (DDIG * NT)        // 360 phase-A units

#define BCH  18                 // phase-B chunks per b
#define BN   (NCAP / BCH)       // 64
#define NUB  (BSZ * BCH)        // 288 phase-B units
#define NUC  (BSZ * DDIG)       // 160 phase-C units

#define GRID 296                // 2 CTAs/SM: all resident (CTAS_ACTIVE{2:148})
#define NTHR 512

// Scratch (device globals; zero-init at load; g_T re-zeroed every call)
__device__ __align__(16) float g_U  [BSZ * DDIG * NCAP * DD];   // 11.8 MB
__device__ __align__(16) float g_T  [BSZ * DDIG * DD];
__device__ __align__(16) float g_wgt[BSZ * DDIG * NCAP];
__device__ unsigned long long g_bar[2];                         // monotonic tickets

// ---- software grid barrier: monotonic ticket, graph-replay safe ----
__device__ __forceinline__ void grid_barrier(int id)
{
    __syncthreads();
    __threadfence();
    if (threadIdx.x == 0) {
        const unsigned long long old = atomicAdd(&g_bar[id], 1ULL);
        const unsigned long long tgt = (old / GRID + 1ULL) * (unsigned long long)GRID;
        unsigned long long v;
        do {
            asm volatile("ld.global.cg.u64 %0, [%1];" : "=l"(v) : "l"(g_bar + id));
            if (v < tgt) __nanosleep(128);
        } while (v < tgt);
    }
    __syncthreads();
}

// -------------------------------------------------------------------------
// Persistent fused kernel, 512 threads: votes+T | barrier | softmax wgt |
// barrier | combine+squash. One launch, no gaps, 32 warps/SM.
// -------------------------------------------------------------------------
__global__ __launch_bounds__(NTHR, 2) void fused_caps(
    const float* __restrict__ u,   // [B][N][DP]
    const float* __restrict__ W,   // [D][N][DD][DP]
    const float* __restrict__ Bp,  // [D][1][N]
    float* __restrict__ out)       // [B][D][DD]
{
    __shared__ __align__(16) char smraw[32768];
    const int t = threadIdx.x;

    // ================= Phase A: votes + atomic T =========================
    {
        float (*us)[TILE_N][DP] = reinterpret_cast<float(*)[TILE_N][DP]>(smraw);    // 16 KB
        float (*red)[16][DD]    = reinterpret_cast<float(*)[16][DD]>(smraw + 16384); // 16 KB

        const int j    = t & 15;
        const int nl   = t >> 4;          // 0..31
        const int lane = t & 31;
        const int w    = t >> 5;          // 0..15; warp w covers nl {2w, 2w+1}

        for (int unit = blockIdx.x; unit < NUA; unit += GRID) {
            const int d  = unit % DDIG;
            const int n0 = (unit / DDIG) * TILE_N;
            const int n  = n0 + nl;

            __syncthreads();   // smem reuse guard across units

            const float4* wp = reinterpret_cast<const float4*>(
                W + ((size_t)(d * NCAP + n) * DD + j) * DP);
            const float4 w0 = wp[0];
            const float4 w1 = wp[1];

            // stage u tile: 16b x 32n x 8 = 1024 f4; 2 per thread
            #pragma unroll
            for (int it = 0; it < 2; ++it) {
                const int idx = it * NTHR + t;
                const int b   = idx >> 6;       // 64 f4 per b
                const int rm  = idx & 63;
                reinterpret_cast<float4*>(&us[b][0][0])[rm] =
                    reinterpret_cast<const float4*>(
                        u + (size_t)b * NCAP * DP + (size_t)n0 * DP)[rm];
            }
            __syncthreads();

            #pragma unroll
            for (int b = 0; b < BSZ; ++b) {
                const float4* up = reinterpret_cast<const float4*>(&us[b][nl][0]);
                const float4 u0 = up[0];
                const float4 u1 = up[1];
                const float acc = w0.x * u0.x + w0.y * u0.y + w0.z * u0.z + w0.w * u0.w
                                + w1.x * u1.x + w1.y * u1.y + w1.z * u1.z + w1.w * u1.w;
                g_U[((size_t)(b * DDIG + d) * NCAP + n) * DD + j] = acc;

                const float ps = acc + __shfl_xor_sync(0xffffffffu, acc, 16);
                if (lane < 16) red[b][w][lane] = ps;   // lane == j
            }
            __syncthreads();

            if (t < BSZ * DD) {
                const int b2 = t >> 4;
                const int j2 = t & 15;
                float s = 0.f;
                #pragma unroll
                for (int ww = 0; ww < 16; ++ww) s += red[b2][ww][j2];
                atomicAdd(&g_T[(b2 * DDIG + d) * DD + j2], s);
            }
        }
    }

    grid_barrier(0);

    // ================= Phase B: softmax weights ==========================
    {
        float* Ts        = reinterpret_cast<float*>(smraw);              // 160 f
        float (*a_s)[12] = reinterpret_cast<float(*)[12]>(smraw + 1024); // 64x12

        const float inv_sqrt8 = 0.3535533905932738f;

        for (int unit = blockIdx.x; unit < NUB; unit += GRID) {
            const int b  = unit / BCH;
            const int ch = unit % BCH;
            const int nb = ch * BN;

            __syncthreads();
            if (t < DDIG * DD) Ts[t] = __ldcg(&g_T[b * DDIG * DD + t]);
            __syncthreads();

            // 640 rows (d*64+nl); t covers r0=t, r1=t+512 (t<128)
            #pragma unroll
            for (int rr = 0; rr < 2; ++rr) {
                const int r = rr * NTHR + t;
                if (r < DDIG * BN) {
                    const int d  = r >> 6;
                    const int nl = r & 63;
                    const float4* p = reinterpret_cast<const float4*>(
                        g_U + ((size_t)(b * DDIG + d) * NCAP + nb + nl) * DD);
                    const float4 v0 = p[0], v1 = p[1], v2 = p[2], v3 = p[3];
                    const float* T = Ts + d * DD;
                    a_s[nl][d] =
                        (T[0]  * v0.x + T[1]  * v0.y + T[2]  * v0.z + T[3]  * v0.w
                       + T[4]  * v1.x + T[5]  * v1.y + T[6]  * v1.z + T[7]  * v1.w
                       + T[8]  * v2.x + T[9]  * v2.y + T[10] * v2.z + T[11] * v2.w
                       + T[12] * v3.x + T[13] * v3.y + T[14] * v3.z + T[15] * v3.w)
                       * inv_sqrt8;
                }
            }
            __syncthreads();

            if (t < BN) {
                const int n2 = nb + t;
                float a[DDIG];
                #pragma unroll
                for (int d = 0; d < DDIG; ++d) a[d] = a_s[t][d];
                float m = a[0];
                #pragma unroll
                for (int d = 1; d < DDIG; ++d) m = fmaxf(m, a[d]);
                float denom = 0.f;
                #pragma unroll
                for (int d = 0; d < DDIG; ++d) { a[d] = __expf(a[d] - m); denom += a[d]; }
                const float rden = 1.f / denom;
                #pragma unroll
                for (int d = 0; d < DDIG; ++d)
                    g_wgt[((size_t)(b * DDIG + d)) * NCAP + n2] =
                        a[d] * rden + __ldg(&Bp[(size_t)d * NCAP + n2]);
            }
        }
    }

    grid_barrier(1);

    // reset T for next call (all phase-B reads done; phase C never reads T)
    for (int idx = blockIdx.x * NTHR + t; idx < BSZ * DDIG * DD; idx += GRID * NTHR)
        g_T[idx] = 0.f;

    // ================= Phase C: combine + squash =========================
    {
        float*  wgs       = reinterpret_cast<float*>(smraw);               // 4608 B
        float4 (*redc)[4] = reinterpret_cast<float4(*)[4]>(smraw + 4608);  // 16x4 f4
        float*  Ssm       = reinterpret_cast<float*>(smraw + 5632);        // 16 f
        float*  coef      = reinterpret_cast<float*>(smraw + 5696);        // 1 f

        const int jq   = t & 3;
        const int ng   = t >> 2;          // 0..127
        const int lane = t & 31;
        const int w5   = t >> 5;          // 0..15

        for (int unit = blockIdx.x; unit < NUC; unit += GRID) {
            const int bd = unit;          // b*DDIG + d

            __syncthreads();
            for (int idx = t; idx < NCAP / 4; idx += NTHR)
                reinterpret_cast<float4*>(wgs)[idx] =
                    __ldcg(reinterpret_cast<const float4*>(g_wgt + (size_t)bd * NCAP) + idx);
            __syncthreads();

            float4 acc = make_float4(0.f, 0.f, 0.f, 0.f);
            #pragma unroll
            for (int k = 0; k < NCAP / 128; ++k) {     // 9 iters
                const int n = k * 128 + ng;
                const float4 v = *reinterpret_cast<const float4*>(
                    g_U + ((size_t)bd * NCAP + n) * DD + jq * 4);
                const float wv = wgs[n];
                acc.x += wv * v.x;
                acc.y += wv * v.y;
                acc.z += wv * v.z;
                acc.w += wv * v.w;
            }

            // reduce over ng within warp (warp = 8 ng x 4 jq): strides 4,8,16
            #pragma unroll
            for (int off = 4; off <= 16; off <<= 1) {
                acc.x += __shfl_xor_sync(0xffffffffu, acc.x, off);
                acc.y += __shfl_xor_sync(0xffffffffu, acc.y, off);
                acc.z += __shfl_xor_sync(0xffffffffu, acc.z, off);
                acc.w += __shfl_xor_sync(0xffffffffu, acc.w, off);
            }
            if (lane < 4) redc[w5][lane] = acc;        // lane == jq
            __syncthreads();

            if (t < 4) {
                float4 s = make_float4(0.f, 0.f, 0.f, 0.f);
                #pragma unroll
                for (int ww = 0; ww < 16; ++ww) {
                    const float4 v = redc[ww][t];
                    s.x += v.x; s.y += v.y; s.z += v.z; s.w += v.w;
                }
                Ssm[t * 4 + 0] = s.x;
                Ssm[t * 4 + 1] = s.y;
                Ssm[t * 4 + 2] = s.z;
                Ssm[t * 4 + 3] = s.w;
            }
            __syncthreads();
            if (t == 0) {
                float nn = 0.f;
                #pragma unroll
                for (int jj = 0; jj < DD; ++jj) nn += Ssm[jj] * Ssm[jj];
                const float norm = sqrtf(nn);
                const float EPS  = 1e-7f;
                coef[0] = (1.f - 1.f / (__expf(norm) + EPS)) / (norm + EPS);
            }
            __syncthreads();
            if (t < DD)
                out[(size_t)bd * DD + t] = coef[0] * Ssm[t];
        }
    }
}

// -------------------------------------------------------------------------
extern "C" void kernel_launch(void* const* d_in, const int* in_sizes, int n_in,
                              void* d_out, int out_size)
{
    const float* u  = (const float*)d_in[0];   // primary_caps [16,1152,8]
    const float* W  = (const float*)d_in[1];   // W            [10,1152,16,8]
    const float* Bp = (const float*)d_in[2];   // B_prior      [10,1,1152]
    float* out      = (float*)d_out;           // [16,10,16]

    (void)in_sizes; (void)n_in; (void)out_size;

    fused_caps<<<GRID, NTHR>>>(u, W, Bp, out);
}